// round 5
// baseline (speedup 1.0000x reference)
#include <cuda_runtime.h>
#include <cuda_bf16.h>
#include <math.h>
#include <cstdint>
#include <cstddef>

#define NN       50000
#define EE       800000
#define ETOT     (EE + NN)
#define FDIM     128

// ---------------- scratch ----------------
__device__ float g_bufA[(size_t)NN * FDIM];
__device__ float g_bufB[(size_t)NN * FDIM];
__device__ float g_es[NN * 2];
__device__ float g_ed[NN * 2];
__device__ int   g_rowptr[NN + 1];
__device__ int   g_wp[NN];
__device__ int   g_col[ETOT];

// ---------------- CSR build ----------------
__global__ void zero_counts_kernel(int n) {
    int i = blockIdx.x * blockDim.x + threadIdx.x;
    if (i < n) g_wp[i] = 0;
}

__global__ void hist_kernel(const int* __restrict__ ei, int E, int n) {
    int e = blockIdx.x * blockDim.x + threadIdx.x;
    int etot = E + n;
    if (e >= etot) return;
    int d = (e < E) ? ei[E + e] : (e - E);
    atomicAdd(&g_wp[d], 1);
}

__global__ __launch_bounds__(1024) void scan_kernel(int n) {
    __shared__ int wsum[32];
    __shared__ int carry_sh;
    int lane = threadIdx.x & 31, wid = threadIdx.x >> 5;
    if (threadIdx.x == 0) carry_sh = 0;
    __syncthreads();
    for (int base = 0; base < n; base += 4096) {
        int idx = base + threadIdx.x * 4;
        int v0 = (idx + 0 < n) ? g_wp[idx + 0] : 0;
        int v1 = (idx + 1 < n) ? g_wp[idx + 1] : 0;
        int v2 = (idx + 2 < n) ? g_wp[idx + 2] : 0;
        int v3 = (idx + 3 < n) ? g_wp[idx + 3] : 0;
        int tsum = v0 + v1 + v2 + v3;
        int x = tsum;
#pragma unroll
        for (int off = 1; off < 32; off <<= 1) {
            int y = __shfl_up_sync(0xffffffffu, x, off);
            if (lane >= off) x += y;
        }
        if (lane == 31) wsum[wid] = x;
        __syncthreads();
        if (wid == 0) {
            int ws = wsum[lane];
#pragma unroll
            for (int off = 1; off < 32; off <<= 1) {
                int y = __shfl_up_sync(0xffffffffu, ws, off);
                if (lane >= off) ws += y;
            }
            wsum[lane] = ws;
        }
        __syncthreads();
        int carry = carry_sh;
        int excl = carry + (wid ? wsum[wid - 1] : 0) + (x - tsum);
        if (idx + 0 < n) { g_rowptr[idx + 0] = excl; g_wp[idx + 0] = excl; } excl += v0;
        if (idx + 1 < n) { g_rowptr[idx + 1] = excl; g_wp[idx + 1] = excl; } excl += v1;
        if (idx + 2 < n) { g_rowptr[idx + 2] = excl; g_wp[idx + 2] = excl; } excl += v2;
        if (idx + 3 < n) { g_rowptr[idx + 3] = excl; g_wp[idx + 3] = excl; }
        int total = wsum[31];
        __syncthreads();
        if (threadIdx.x == 0) carry_sh = carry + total;
        __syncthreads();
    }
    if (threadIdx.x == 0) g_rowptr[n] = carry_sh;
}

__global__ void scatter_kernel(const int* __restrict__ ei, int E, int n) {
    int e = blockIdx.x * blockDim.x + threadIdx.x;
    int etot = E + n;
    if (e >= etot) return;
    int s, d;
    if (e < E) { s = ei[e]; d = ei[E + e]; }
    else       { s = e - E; d = s; }
    int p = atomicAdd(&g_wp[d], 1);
    g_col[p] = s;
}

// ---------------- cp.async helpers ----------------
__device__ __forceinline__ void cp_async16(uint32_t smem_dst, const void* gptr, int src_sz) {
    asm volatile("cp.async.cg.shared.global [%0], [%1], 16, %2;\n"
                 :: "r"(smem_dst), "l"(gptr), "r"(src_sz));
}
__device__ __forceinline__ void cp_commit() { asm volatile("cp.async.commit_group;\n"); }
template<int N> __device__ __forceinline__ void cp_wait() {
    asm volatile("cp.async.wait_group %0;\n" :: "n"(N));
}

// ---------------- SGEMM (cp.async double-buffered) + e epilogue ----------------
// C[M,128] = A[M,128] @ W[128,128]; es/ed fused.
__global__ __launch_bounds__(256) void sgemm128_kernel(
    const float* __restrict__ A, const float* __restrict__ W,
    const float* __restrict__ av_src, const float* __restrict__ av_dst,
    float* __restrict__ C, int M)
{
    __shared__ float As[2][128][16];   // untransposed; reads are warp-broadcast
    __shared__ float Bs[2][16][128];
    int block_row = blockIdx.x * 128;
    int tid = threadIdx.x;
    int tr = tid >> 4;       // 0..15
    int tc = tid & 15;       // 0..15

    // chunk assignment: A tile = 512 x 16B chunks, B tile = 512 x 16B chunks; 2 each/thread
    int ar0 = tid >> 2,            ac0 = (tid & 3) * 4;
    int ar1 = (tid + 256) >> 2,    ac1 = ac0;
    int br0 = tid >> 5,            bc0 = (tid & 31) * 4;
    int br1 = (tid + 256) >> 5,    bc1 = bc0;
    int sz_a0 = (block_row + ar0 < M) ? 16 : 0;
    int sz_a1 = (block_row + ar1 < M) ? 16 : 0;

    uint32_t as_base = (uint32_t)__cvta_generic_to_shared(&As[0][0][0]);
    uint32_t bs_base = (uint32_t)__cvta_generic_to_shared(&Bs[0][0][0]);

    float acc[8][8];
#pragma unroll
    for (int i = 0; i < 8; i++)
#pragma unroll
        for (int j = 0; j < 8; j++) acc[i][j] = 0.f;

    auto issue = [&](int s, int k0) {
        uint32_t asb = as_base + s * (128 * 16 * 4);
        uint32_t bsb = bs_base + s * (16 * 128 * 4);
        cp_async16(asb + (ar0 * 16 + ac0) * 4, &A[(size_t)(block_row + ar0) * 128 + k0 + ac0], sz_a0);
        cp_async16(asb + (ar1 * 16 + ac1) * 4, &A[(size_t)(block_row + ar1) * 128 + k0 + ac1], sz_a1);
        cp_async16(bsb + (br0 * 128 + bc0) * 4, &W[(size_t)(k0 + br0) * 128 + bc0], 16);
        cp_async16(bsb + (br1 * 128 + bc1) * 4, &W[(size_t)(k0 + br1) * 128 + bc1], 16);
    };

    issue(0, 0);
    cp_commit();
#pragma unroll
    for (int t = 0; t < 8; t++) {
        if (t < 7) { issue((t + 1) & 1, (t + 1) * 16); cp_commit(); cp_wait<1>(); }
        else       { cp_wait<0>(); }
        __syncthreads();
        int s = t & 1;
#pragma unroll
        for (int k = 0; k < 16; k++) {
            float b[8];
            float4 b0 = *reinterpret_cast<const float4*>(&Bs[s][k][tc * 8]);
            float4 b1 = *reinterpret_cast<const float4*>(&Bs[s][k][tc * 8 + 4]);
            b[0]=b0.x;b[1]=b0.y;b[2]=b0.z;b[3]=b0.w;b[4]=b1.x;b[5]=b1.y;b[6]=b1.z;b[7]=b1.w;
            float a[8];
#pragma unroll
            for (int i = 0; i < 8; i++) a[i] = As[s][tr * 8 + i][k];
#pragma unroll
            for (int i = 0; i < 8; i++)
#pragma unroll
                for (int j = 0; j < 8; j++)
                    acc[i][j] += a[i] * b[j];
        }
        __syncthreads();
    }

    // store C
#pragma unroll
    for (int i = 0; i < 8; i++) {
        int gr = block_row + tr * 8 + i;
        if (gr < M) {
            float4 v0 = make_float4(acc[i][0], acc[i][1], acc[i][2], acc[i][3]);
            float4 v1 = make_float4(acc[i][4], acc[i][5], acc[i][6], acc[i][7]);
            *reinterpret_cast<float4*>(&C[(size_t)gr * 128 + tc * 8])     = v0;
            *reinterpret_cast<float4*>(&C[(size_t)gr * 128 + tc * 8 + 4]) = v1;
        }
    }

    // fused e_src / e_dst epilogue (head0: tc<8, head1: tc>=8)
    float4 s0 = *reinterpret_cast<const float4*>(&av_src[tc * 8]);
    float4 s1 = *reinterpret_cast<const float4*>(&av_src[tc * 8 + 4]);
    float4 d0 = *reinterpret_cast<const float4*>(&av_dst[tc * 8]);
    float4 d1 = *reinterpret_cast<const float4*>(&av_dst[tc * 8 + 4]);
#pragma unroll
    for (int i = 0; i < 8; i++) {
        float ps = acc[i][0]*s0.x + acc[i][1]*s0.y + acc[i][2]*s0.z + acc[i][3]*s0.w
                 + acc[i][4]*s1.x + acc[i][5]*s1.y + acc[i][6]*s1.z + acc[i][7]*s1.w;
        float pd = acc[i][0]*d0.x + acc[i][1]*d0.y + acc[i][2]*d0.z + acc[i][3]*d0.w
                 + acc[i][4]*d1.x + acc[i][5]*d1.y + acc[i][6]*d1.z + acc[i][7]*d1.w;
#pragma unroll
        for (int off = 1; off < 8; off <<= 1) {
            ps += __shfl_xor_sync(0xffffffffu, ps, off);
            pd += __shfl_xor_sync(0xffffffffu, pd, off);
        }
        int row = block_row + tr * 8 + i;
        if (row < M) {
            if (tc == 0) { g_es[2 * row]     = ps; g_ed[2 * row]     = pd; }
            if (tc == 8) { g_es[2 * row + 1] = ps; g_ed[2 * row + 1] = pd; }
        }
    }
}

__device__ __forceinline__ float lrelu(float x) { return x > 0.f ? x : 0.2f * x; }

// ---------------- fused softmax-aggregate (warp per dst node) ----------------
__global__ __launch_bounds__(256) void agg_kernel(
    const float* __restrict__ h, const float* __restrict__ bias,
    float* __restrict__ out, int n)
{
    int w = (blockIdx.x * blockDim.x + threadIdx.x) >> 5;
    int lane = threadIdx.x & 31;
    if (w >= n) return;
    int start = g_rowptr[w], end = g_rowptr[w + 1];
    int deg = end - start;
    const float2* es2 = reinterpret_cast<const float2*>(g_es);
    const float2* ed2 = reinterpret_cast<const float2*>(g_ed);
    float2 ed = ed2[w];

    float acc0 = 0.f, acc1 = 0.f, acc2 = 0.f, acc3 = 0.f;
    float den0 = 0.f, den1 = 0.f;
    const float4* h4 = reinterpret_cast<const float4*>(h);
    bool head0 = (lane < 16);

    if (deg <= 32) {
        // single-chunk fast path: metadata loaded exactly once, logits in regs
        int s = 0; float l0 = -3.0e38f, l1 = -3.0e38f;
        if (lane < deg) {
            s = g_col[start + lane];
            float2 es = es2[s];
            l0 = lrelu(es.x + ed.x);
            l1 = lrelu(es.y + ed.y);
        }
        float m0 = l0, m1 = l1;
#pragma unroll
        for (int o = 16; o; o >>= 1) {
            m0 = fmaxf(m0, __shfl_xor_sync(0xffffffffu, m0, o));
            m1 = fmaxf(m1, __shfl_xor_sync(0xffffffffu, m1, o));
        }
        float w0 = 0.f, w1 = 0.f;
        if (lane < deg) { w0 = __expf(l0 - m0); w1 = __expf(l1 - m1); }
        den0 = w0; den1 = w1;
#pragma unroll 4
        for (int k = 0; k < deg; k++) {
            int   ss  = __shfl_sync(0xffffffffu, s,  k);
            float wk0 = __shfl_sync(0xffffffffu, w0, k);
            float wk1 = __shfl_sync(0xffffffffu, w1, k);
            float wk  = head0 ? wk0 : wk1;
            float4 hv = h4[(size_t)ss * 32 + lane];
            acc0 += wk * hv.x; acc1 += wk * hv.y;
            acc2 += wk * hv.z; acc3 += wk * hv.w;
        }
    } else {
        // general path: max pass, then chunked accumulate
        float m0 = -3.0e38f, m1 = -3.0e38f;
        for (int j = start + lane; j < end; j += 32) {
            int s = g_col[j];
            float2 es = es2[s];
            m0 = fmaxf(m0, lrelu(es.x + ed.x));
            m1 = fmaxf(m1, lrelu(es.y + ed.y));
        }
#pragma unroll
        for (int o = 16; o; o >>= 1) {
            m0 = fmaxf(m0, __shfl_xor_sync(0xffffffffu, m0, o));
            m1 = fmaxf(m1, __shfl_xor_sync(0xffffffffu, m1, o));
        }
        for (int chunk = start; chunk < end; chunk += 32) {
            int j = chunk + lane;
            int s = 0; float w0 = 0.f, w1 = 0.f;
            if (j < end) {
                int sc = g_col[j];
                s = sc;
                float2 es = es2[sc];
                w0 = __expf(lrelu(es.x + ed.x) - m0);
                w1 = __expf(lrelu(es.y + ed.y) - m1);
            }
            den0 += w0; den1 += w1;
            int cnt = min(32, end - chunk);
#pragma unroll 4
            for (int k = 0; k < cnt; k++) {
                int   ss  = __shfl_sync(0xffffffffu, s,  k);
                float wk0 = __shfl_sync(0xffffffffu, w0, k);
                float wk1 = __shfl_sync(0xffffffffu, w1, k);
                float wk  = head0 ? wk0 : wk1;
                float4 hv = h4[(size_t)ss * 32 + lane];
                acc0 += wk * hv.x; acc1 += wk * hv.y;
                acc2 += wk * hv.z; acc3 += wk * hv.w;
            }
        }
    }

#pragma unroll
    for (int o = 16; o; o >>= 1) {
        den0 += __shfl_xor_sync(0xffffffffu, den0, o);
        den1 += __shfl_xor_sync(0xffffffffu, den1, o);
    }
    float inv = 1.0f / (head0 ? den0 : den1);
    float4 bb = reinterpret_cast<const float4*>(bias)[lane];
    float o0 = acc0 * inv + bb.x;
    float o1 = acc1 * inv + bb.y;
    float o2 = acc2 * inv + bb.z;
    float o3 = acc3 * inv + bb.w;
    o0 = o0 > 0.f ? o0 : expm1f(o0);
    o1 = o1 > 0.f ? o1 : expm1f(o1);
    o2 = o2 > 0.f ? o2 : expm1f(o2);
    o3 = o3 > 0.f ? o3 : expm1f(o3);
    reinterpret_cast<float4*>(out)[(size_t)w * 32 + lane] = make_float4(o0, o1, o2, o3);
}

// ---------------- host ----------------
extern "C" void kernel_launch(void* const* d_in, const int* in_sizes, int n_in,
                              void* d_out, int out_size)
{
    const float* x   = (const float*)d_in[0];
    const int*   ei  = (const int*)d_in[1];
    const float* W1  = (const float*)d_in[2];
    const float* as1 = (const float*)d_in[3];
    const float* ad1 = (const float*)d_in[4];
    const float* b1  = (const float*)d_in[5];
    const float* W2  = (const float*)d_in[6];
    const float* as2 = (const float*)d_in[7];
    const float* ad2 = (const float*)d_in[8];
    const float* b2  = (const float*)d_in[9];
    const float* W3  = (const float*)d_in[10];
    const float* as3 = (const float*)d_in[11];
    const float* ad3 = (const float*)d_in[12];
    const float* b3  = (const float*)d_in[13];
    float*       out = (float*)d_out;

    int n = in_sizes[0] / FDIM;          // 50000
    int E = in_sizes[1] / 2;             // 800000

    void* pA; cudaGetSymbolAddress(&pA, g_bufA);
    void* pB; cudaGetSymbolAddress(&pB, g_bufB);
    float* bufA = (float*)pA;
    float* bufB = (float*)pB;

    int nblkNodes = (n + 255) / 256;
    int nblkEdges = (E + n + 255) / 256;
    int nblkWarp  = (n * 32 + 255) / 256;
    int nblkGemm  = (n + 127) / 128;

    // launches 0..2: CSR front half
    zero_counts_kernel<<<nblkNodes, 256>>>(n);
    hist_kernel<<<nblkEdges, 256>>>(ei, E, n);
    scan_kernel<<<1, 1024>>>(n);
    // launch 3: sgemm1 (profiled by ncu capture offset)
    sgemm128_kernel<<<nblkGemm, 256>>>(x, W1, as1, ad1, bufA, n);
    // launch 4: scatter completes CSR before agg1
    scatter_kernel<<<nblkEdges, 256>>>(ei, E, n);
    // launch 5: agg1
    agg_kernel<<<nblkWarp, 256>>>(bufA, b1, bufB, n);
    // layer 2
    sgemm128_kernel<<<nblkGemm, 256>>>(bufB, W2, as2, ad2, bufA, n);
    agg_kernel<<<nblkWarp, 256>>>(bufA, b2, bufB, n);
    // layer 3
    sgemm128_kernel<<<nblkGemm, 256>>>(bufB, W3, as3, ad3, bufA, n);
    agg_kernel<<<nblkWarp, 256>>>(bufA, b3, out, n);
}

// round 6
// speedup vs baseline: 1.1651x; 1.1651x over previous
#include <cuda_runtime.h>
#include <cuda_bf16.h>
#include <math.h>
#include <cstdint>
#include <cstddef>

#define NN       50000
#define EE       800000
#define ETOT     (EE + NN)
#define FDIM     128

// ---------------- scratch ----------------
__device__ float g_bufA[(size_t)NN * FDIM];
__device__ float g_bufB[(size_t)NN * FDIM];
__device__ float g_es[NN * 2];
__device__ float g_ed[NN * 2];
__device__ int   g_rowptr[NN + 1];
__device__ int   g_wp[NN];
__device__ int   g_col[ETOT];

// ---------------- CSR build ----------------
__global__ void zero_counts_kernel(int n) {
    int i = blockIdx.x * blockDim.x + threadIdx.x;
    if (i < n) g_wp[i] = 0;
}

__global__ void hist_kernel(const int* __restrict__ ei, int E, int n) {
    int e = blockIdx.x * blockDim.x + threadIdx.x;
    int etot = E + n;
    if (e >= etot) return;
    int d = (e < E) ? ei[E + e] : (e - E);
    atomicAdd(&g_wp[d], 1);
}

__global__ __launch_bounds__(1024) void scan_kernel(int n) {
    __shared__ int wsum[32];
    __shared__ int carry_sh;
    int lane = threadIdx.x & 31, wid = threadIdx.x >> 5;
    if (threadIdx.x == 0) carry_sh = 0;
    __syncthreads();
    for (int base = 0; base < n; base += 4096) {
        int idx = base + threadIdx.x * 4;
        int v0 = (idx + 0 < n) ? g_wp[idx + 0] : 0;
        int v1 = (idx + 1 < n) ? g_wp[idx + 1] : 0;
        int v2 = (idx + 2 < n) ? g_wp[idx + 2] : 0;
        int v3 = (idx + 3 < n) ? g_wp[idx + 3] : 0;
        int tsum = v0 + v1 + v2 + v3;
        int x = tsum;
#pragma unroll
        for (int off = 1; off < 32; off <<= 1) {
            int y = __shfl_up_sync(0xffffffffu, x, off);
            if (lane >= off) x += y;
        }
        if (lane == 31) wsum[wid] = x;
        __syncthreads();
        if (wid == 0) {
            int ws = wsum[lane];
#pragma unroll
            for (int off = 1; off < 32; off <<= 1) {
                int y = __shfl_up_sync(0xffffffffu, ws, off);
                if (lane >= off) ws += y;
            }
            wsum[lane] = ws;
        }
        __syncthreads();
        int carry = carry_sh;
        int excl = carry + (wid ? wsum[wid - 1] : 0) + (x - tsum);
        if (idx + 0 < n) { g_rowptr[idx + 0] = excl; g_wp[idx + 0] = excl; } excl += v0;
        if (idx + 1 < n) { g_rowptr[idx + 1] = excl; g_wp[idx + 1] = excl; } excl += v1;
        if (idx + 2 < n) { g_rowptr[idx + 2] = excl; g_wp[idx + 2] = excl; } excl += v2;
        if (idx + 3 < n) { g_rowptr[idx + 3] = excl; g_wp[idx + 3] = excl; }
        int total = wsum[31];
        __syncthreads();
        if (threadIdx.x == 0) carry_sh = carry + total;
        __syncthreads();
    }
    if (threadIdx.x == 0) g_rowptr[n] = carry_sh;
}

__global__ void scatter_kernel(const int* __restrict__ ei, int E, int n) {
    int e = blockIdx.x * blockDim.x + threadIdx.x;
    int etot = E + n;
    if (e >= etot) return;
    int s, d;
    if (e < E) { s = ei[e]; d = ei[E + e]; }
    else       { s = e - E; d = s; }
    int p = atomicAdd(&g_wp[d], 1);
    g_col[p] = s;
}

// ---------------- SGEMM + fused e epilogue ----------------
// C[M,128] = A[M,128] @ W[128,128].  BM=64, BN=128, BK=16.
// 256 threads, 4x8 micro-tile -> ~75 regs -> 3 CTAs/SM.
__global__ __launch_bounds__(256) void sgemm128_kernel(
    const float* __restrict__ A, const float* __restrict__ W,
    const float* __restrict__ av_src, const float* __restrict__ av_dst,
    float* __restrict__ C, int M)
{
    __shared__ float As[16][68];    // transposed A tile (k-major), padded
    __shared__ float Bs[16][132];
    int block_row = blockIdx.x * 64;
    int tid = threadIdx.x;
    int tr = tid >> 4;       // 0..15 -> rows tr*4 .. tr*4+3
    int tc = tid & 15;       // 0..15 -> cols tc*8 .. tc*8+7

    float acc[4][8];
#pragma unroll
    for (int i = 0; i < 4; i++)
#pragma unroll
        for (int j = 0; j < 8; j++) acc[i][j] = 0.f;

    // A-tile load assignment: 64 rows x 16 cols = 256 float4s, 1/thread
    int ar = tid >> 2;
    int ac = (tid & 3) * 4;
    // B-tile: 16 rows x 128 cols = 512 float4s, 2/thread
    int br0 = tid >> 5,         bc0 = (tid & 31) * 4;
    int br1 = (tid + 256) >> 5, bc1 = bc0;

    for (int k0 = 0; k0 < 128; k0 += 16) {
        int gr = block_row + ar;
        float4 v = make_float4(0.f, 0.f, 0.f, 0.f);
        if (gr < M) v = *reinterpret_cast<const float4*>(&A[(size_t)gr * 128 + k0 + ac]);
        As[ac + 0][ar] = v.x;
        As[ac + 1][ar] = v.y;
        As[ac + 2][ar] = v.z;
        As[ac + 3][ar] = v.w;
        float4 w0 = *reinterpret_cast<const float4*>(&W[(size_t)(k0 + br0) * 128 + bc0]);
        *reinterpret_cast<float4*>(&Bs[br0][bc0]) = w0;
        float4 w1 = *reinterpret_cast<const float4*>(&W[(size_t)(k0 + br1) * 128 + bc1]);
        *reinterpret_cast<float4*>(&Bs[br1][bc1]) = w1;
        __syncthreads();
#pragma unroll
        for (int k = 0; k < 16; k++) {
            float4 av4 = *reinterpret_cast<const float4*>(&As[k][tr * 4]);
            float4 b0  = *reinterpret_cast<const float4*>(&Bs[k][tc * 8]);
            float4 b1  = *reinterpret_cast<const float4*>(&Bs[k][tc * 8 + 4]);
            float a[4] = {av4.x, av4.y, av4.z, av4.w};
            float b[8] = {b0.x, b0.y, b0.z, b0.w, b1.x, b1.y, b1.z, b1.w};
#pragma unroll
            for (int i = 0; i < 4; i++)
#pragma unroll
                for (int j = 0; j < 8; j++)
                    acc[i][j] += a[i] * b[j];
        }
        __syncthreads();
    }

    // store C
#pragma unroll
    for (int i = 0; i < 4; i++) {
        int gr = block_row + tr * 4 + i;
        if (gr < M) {
            float4 v0 = make_float4(acc[i][0], acc[i][1], acc[i][2], acc[i][3]);
            float4 v1 = make_float4(acc[i][4], acc[i][5], acc[i][6], acc[i][7]);
            *reinterpret_cast<float4*>(&C[(size_t)gr * 128 + tc * 8])     = v0;
            *reinterpret_cast<float4*>(&C[(size_t)gr * 128 + tc * 8 + 4]) = v1;
        }
    }

    // fused e_src / e_dst epilogue (tc<8 -> head0, tc>=8 -> head1)
    float4 s0 = *reinterpret_cast<const float4*>(&av_src[tc * 8]);
    float4 s1 = *reinterpret_cast<const float4*>(&av_src[tc * 8 + 4]);
    float4 d0 = *reinterpret_cast<const float4*>(&av_dst[tc * 8]);
    float4 d1 = *reinterpret_cast<const float4*>(&av_dst[tc * 8 + 4]);
#pragma unroll
    for (int i = 0; i < 4; i++) {
        float ps = acc[i][0]*s0.x + acc[i][1]*s0.y + acc[i][2]*s0.z + acc[i][3]*s0.w
                 + acc[i][4]*s1.x + acc[i][5]*s1.y + acc[i][6]*s1.z + acc[i][7]*s1.w;
        float pd = acc[i][0]*d0.x + acc[i][1]*d0.y + acc[i][2]*d0.z + acc[i][3]*d0.w
                 + acc[i][4]*d1.x + acc[i][5]*d1.y + acc[i][6]*d1.z + acc[i][7]*d1.w;
#pragma unroll
        for (int off = 1; off < 8; off <<= 1) {
            ps += __shfl_xor_sync(0xffffffffu, ps, off);
            pd += __shfl_xor_sync(0xffffffffu, pd, off);
        }
        int row = block_row + tr * 4 + i;
        if (row < M) {
            if (tc == 0) { g_es[2 * row]     = ps; g_ed[2 * row]     = pd; }
            if (tc == 8) { g_es[2 * row + 1] = ps; g_ed[2 * row + 1] = pd; }
        }
    }
}

__device__ __forceinline__ float lrelu(float x) { return x > 0.f ? x : 0.2f * x; }

// ---------------- fused softmax-aggregate (warp per dst node) ----------------
__global__ __launch_bounds__(256) void agg_kernel(
    const float* __restrict__ h, const float* __restrict__ bias,
    float* __restrict__ out, int n)
{
    int w = (blockIdx.x * blockDim.x + threadIdx.x) >> 5;
    int lane = threadIdx.x & 31;
    if (w >= n) return;
    int start = g_rowptr[w], end = g_rowptr[w + 1];
    int deg = end - start;
    const float2* es2 = reinterpret_cast<const float2*>(g_es);
    const float2* ed2 = reinterpret_cast<const float2*>(g_ed);
    float2 ed = ed2[w];

    float acc0 = 0.f, acc1 = 0.f, acc2 = 0.f, acc3 = 0.f;
    float den0 = 0.f, den1 = 0.f;
    const float4* h4 = reinterpret_cast<const float4*>(h);
    bool head0 = (lane < 16);

    if (deg <= 32) {
        int s = 0; float l0 = -3.0e38f, l1 = -3.0e38f;
        if (lane < deg) {
            s = g_col[start + lane];
            float2 es = es2[s];
            l0 = lrelu(es.x + ed.x);
            l1 = lrelu(es.y + ed.y);
        }
        float m0 = l0, m1 = l1;
#pragma unroll
        for (int o = 16; o; o >>= 1) {
            m0 = fmaxf(m0, __shfl_xor_sync(0xffffffffu, m0, o));
            m1 = fmaxf(m1, __shfl_xor_sync(0xffffffffu, m1, o));
        }
        float w0 = 0.f, w1 = 0.f;
        if (lane < deg) { w0 = __expf(l0 - m0); w1 = __expf(l1 - m1); }
        den0 = w0; den1 = w1;
#pragma unroll 4
        for (int k = 0; k < deg; k++) {
            int   ss  = __shfl_sync(0xffffffffu, s,  k);
            float wk0 = __shfl_sync(0xffffffffu, w0, k);
            float wk1 = __shfl_sync(0xffffffffu, w1, k);
            float wk  = head0 ? wk0 : wk1;
            float4 hv = h4[(size_t)ss * 32 + lane];
            acc0 += wk * hv.x; acc1 += wk * hv.y;
            acc2 += wk * hv.z; acc3 += wk * hv.w;
        }
    } else {
        float m0 = -3.0e38f, m1 = -3.0e38f;
        for (int j = start + lane; j < end; j += 32) {
            int s = g_col[j];
            float2 es = es2[s];
            m0 = fmaxf(m0, lrelu(es.x + ed.x));
            m1 = fmaxf(m1, lrelu(es.y + ed.y));
        }
#pragma unroll
        for (int o = 16; o; o >>= 1) {
            m0 = fmaxf(m0, __shfl_xor_sync(0xffffffffu, m0, o));
            m1 = fmaxf(m1, __shfl_xor_sync(0xffffffffu, m1, o));
        }
        for (int chunk = start; chunk < end; chunk += 32) {
            int j = chunk + lane;
            int s = 0; float w0 = 0.f, w1 = 0.f;
            if (j < end) {
                int sc = g_col[j];
                s = sc;
                float2 es = es2[sc];
                w0 = __expf(lrelu(es.x + ed.x) - m0);
                w1 = __expf(lrelu(es.y + ed.y) - m1);
            }
            den0 += w0; den1 += w1;
            int cnt = min(32, end - chunk);
#pragma unroll 4
            for (int k = 0; k < cnt; k++) {
                int   ss  = __shfl_sync(0xffffffffu, s,  k);
                float wk0 = __shfl_sync(0xffffffffu, w0, k);
                float wk1 = __shfl_sync(0xffffffffu, w1, k);
                float wk  = head0 ? wk0 : wk1;
                float4 hv = h4[(size_t)ss * 32 + lane];
                acc0 += wk * hv.x; acc1 += wk * hv.y;
                acc2 += wk * hv.z; acc3 += wk * hv.w;
            }
        }
    }

#pragma unroll
    for (int o = 16; o; o >>= 1) {
        den0 += __shfl_xor_sync(0xffffffffu, den0, o);
        den1 += __shfl_xor_sync(0xffffffffu, den1, o);
    }
    float inv = 1.0f / (head0 ? den0 : den1);
    float4 bb = reinterpret_cast<const float4*>(bias)[lane];
    float o0 = acc0 * inv + bb.x;
    float o1 = acc1 * inv + bb.y;
    float o2 = acc2 * inv + bb.z;
    float o3 = acc3 * inv + bb.w;
    o0 = o0 > 0.f ? o0 : expm1f(o0);
    o1 = o1 > 0.f ? o1 : expm1f(o1);
    o2 = o2 > 0.f ? o2 : expm1f(o2);
    o3 = o3 > 0.f ? o3 : expm1f(o3);
    reinterpret_cast<float4*>(out)[(size_t)w * 32 + lane] = make_float4(o0, o1, o2, o3);
}

// ---------------- host ----------------
extern "C" void kernel_launch(void* const* d_in, const int* in_sizes, int n_in,
                              void* d_out, int out_size)
{
    const float* x   = (const float*)d_in[0];
    const int*   ei  = (const int*)d_in[1];
    const float* W1  = (const float*)d_in[2];
    const float* as1 = (const float*)d_in[3];
    const float* ad1 = (const float*)d_in[4];
    const float* b1  = (const float*)d_in[5];
    const float* W2  = (const float*)d_in[6];
    const float* as2 = (const float*)d_in[7];
    const float* ad2 = (const float*)d_in[8];
    const float* b2  = (const float*)d_in[9];
    const float* W3  = (const float*)d_in[10];
    const float* as3 = (const float*)d_in[11];
    const float* ad3 = (const float*)d_in[12];
    const float* b3  = (const float*)d_in[13];
    float*       out = (float*)d_out;

    int n = in_sizes[0] / FDIM;          // 50000
    int E = in_sizes[1] / 2;             // 800000

    void* pA; cudaGetSymbolAddress(&pA, g_bufA);
    void* pB; cudaGetSymbolAddress(&pB, g_bufB);
    float* bufA = (float*)pA;
    float* bufB = (float*)pB;

    int nblkNodes = (n + 255) / 256;
    int nblkEdges = (E + n + 255) / 256;
    int nblkWarp  = (n * 32 + 255) / 256;
    int nblkGemm  = (n + 63) / 64;

    // launches 0..2: CSR front half
    zero_counts_kernel<<<nblkNodes, 256>>>(n);
    hist_kernel<<<nblkEdges, 256>>>(ei, E, n);
    scan_kernel<<<1, 1024>>>(n);
    // launch 3: sgemm1 (profiled by ncu capture offset)
    sgemm128_kernel<<<nblkGemm, 256>>>(x, W1, as1, ad1, bufA, n);
    // launch 4: scatter completes CSR before agg1
    scatter_kernel<<<nblkEdges, 256>>>(ei, E, n);
    // launch 5: agg1
    agg_kernel<<<nblkWarp, 256>>>(bufA, b1, bufB, n);
    // layer 2
    sgemm128_kernel<<<nblkGemm, 256>>>(bufB, W2, as2, ad2, bufA, n);
    agg_kernel<<<nblkWarp, 256>>>(bufA, b2, bufB, n);
    // layer 3
    sgemm128_kernel<<<nblkGemm, 256>>>(bufB, W3, as3, ad3, bufA, n);
    agg_kernel<<<nblkWarp, 256>>>(bufA, b3, out, n);
}

// round 7
// speedup vs baseline: 1.4840x; 1.2738x over previous
#include <cuda_runtime.h>
#include <cuda_bf16.h>
#include <math.h>
#include <cstdint>
#include <cstddef>

#define NN       50000
#define EE       800000
#define ETOT     (EE + NN)
#define FDIM     128

// ---------------- scratch ----------------
__device__ float g_bufA[(size_t)NN * FDIM];
__device__ float g_bufB[(size_t)NN * FDIM];
__device__ float g_es[NN * 2];
__device__ float g_ed[NN * 2];
__device__ int   g_rowptr[NN + 1];
__device__ int   g_wp[NN];
__device__ int   g_col[ETOT];

// ---------------- CSR build ----------------
__global__ void zero_counts_kernel(int n) {
    int i = blockIdx.x * blockDim.x + threadIdx.x;
    if (i < n) g_wp[i] = 0;
}

__global__ void hist_kernel(const int* __restrict__ ei, int E, int n) {
    int e = blockIdx.x * blockDim.x + threadIdx.x;
    int etot = E + n;
    if (e >= etot) return;
    int d = (e < E) ? ei[E + e] : (e - E);
    atomicAdd(&g_wp[d], 1);
}

__global__ __launch_bounds__(1024) void scan_kernel(int n) {
    __shared__ int wsum[32];
    __shared__ int carry_sh;
    int lane = threadIdx.x & 31, wid = threadIdx.x >> 5;
    if (threadIdx.x == 0) carry_sh = 0;
    __syncthreads();
    for (int base = 0; base < n; base += 4096) {
        int idx = base + threadIdx.x * 4;
        int v0 = (idx + 0 < n) ? g_wp[idx + 0] : 0;
        int v1 = (idx + 1 < n) ? g_wp[idx + 1] : 0;
        int v2 = (idx + 2 < n) ? g_wp[idx + 2] : 0;
        int v3 = (idx + 3 < n) ? g_wp[idx + 3] : 0;
        int tsum = v0 + v1 + v2 + v3;
        int x = tsum;
#pragma unroll
        for (int off = 1; off < 32; off <<= 1) {
            int y = __shfl_up_sync(0xffffffffu, x, off);
            if (lane >= off) x += y;
        }
        if (lane == 31) wsum[wid] = x;
        __syncthreads();
        if (wid == 0) {
            int ws = wsum[lane];
#pragma unroll
            for (int off = 1; off < 32; off <<= 1) {
                int y = __shfl_up_sync(0xffffffffu, ws, off);
                if (lane >= off) ws += y;
            }
            wsum[lane] = ws;
        }
        __syncthreads();
        int carry = carry_sh;
        int excl = carry + (wid ? wsum[wid - 1] : 0) + (x - tsum);
        if (idx + 0 < n) { g_rowptr[idx + 0] = excl; g_wp[idx + 0] = excl; } excl += v0;
        if (idx + 1 < n) { g_rowptr[idx + 1] = excl; g_wp[idx + 1] = excl; } excl += v1;
        if (idx + 2 < n) { g_rowptr[idx + 2] = excl; g_wp[idx + 2] = excl; } excl += v2;
        if (idx + 3 < n) { g_rowptr[idx + 3] = excl; g_wp[idx + 3] = excl; }
        int total = wsum[31];
        __syncthreads();
        if (threadIdx.x == 0) carry_sh = carry + total;
        __syncthreads();
    }
    if (threadIdx.x == 0) g_rowptr[n] = carry_sh;
}

__global__ void scatter_kernel(const int* __restrict__ ei, int E, int n) {
    int e = blockIdx.x * blockDim.x + threadIdx.x;
    int etot = E + n;
    if (e >= etot) return;
    int s, d;
    if (e < E) { s = ei[e]; d = ei[E + e]; }
    else       { s = e - E; d = s; }
    int p = atomicAdd(&g_wp[d], 1);
    g_col[p] = s;
}

// ---------------- tf32 helpers ----------------
__device__ __forceinline__ uint32_t f2tf32(float x) {
    uint32_t r;
    asm("cvt.rna.tf32.f32 %0, %1;" : "=r"(r) : "f"(x));
    return r;
}
__device__ __forceinline__ void mma_tf32(float* c, const uint32_t* a, const uint32_t* b) {
    asm volatile(
        "mma.sync.aligned.m16n8k8.row.col.f32.tf32.tf32.f32 "
        "{%0,%1,%2,%3},{%4,%5,%6,%7},{%8,%9},{%0,%1,%2,%3};"
        : "+f"(c[0]), "+f"(c[1]), "+f"(c[2]), "+f"(c[3])
        : "r"(a[0]), "r"(a[1]), "r"(a[2]), "r"(a[3]), "r"(b[0]), "r"(b[1]));
}

// ---------------- 3xTF32 tensor GEMM + fused e epilogue ----------------
// C[M,128] = A[M,128] @ W[128,128].  CTA tile 128x128, 8 warps (4 row x 2 col).
// Warp-col == attention head for the e epilogue.
__global__ __launch_bounds__(256, 2) void sgemm128_kernel(
    const float* __restrict__ A, const float* __restrict__ W,
    const float* __restrict__ av_src, const float* __restrict__ av_dst,
    float* __restrict__ C, int M)
{
    __shared__ float As[128][36];   // pad 36: A-frag reads conflict-free
    __shared__ float Bs[32][136];   // pad 136: B-frag reads conflict-free
    int block_row = blockIdx.x * 128;
    int tid  = threadIdx.x;
    int lane = tid & 31;
    int warp = tid >> 5;
    int wr = warp >> 1;             // 0..3: rows wr*32 .. +31
    int wc = warp & 1;              // 0..1: cols wc*64 .. +63  (== head)
    int lq = lane >> 2;             // 0..7
    int lr = lane & 3;              // 0..3

    float c[2][8][4];
#pragma unroll
    for (int mt = 0; mt < 2; mt++)
#pragma unroll
        for (int nt = 0; nt < 8; nt++)
#pragma unroll
            for (int i = 0; i < 4; i++) c[mt][nt][i] = 0.f;

    for (int kc = 0; kc < 4; kc++) {
        int k0 = kc * 32;
        // stage A[128][32] and W[32][128] chunk
#pragma unroll
        for (int i = 0; i < 4; i++) {
            int idx = tid + i * 256;
            int ar = idx >> 3, ac4 = (idx & 7) * 4;
            int gr = block_row + ar;
            float4 v = make_float4(0.f, 0.f, 0.f, 0.f);
            if (gr < M) v = *reinterpret_cast<const float4*>(&A[(size_t)gr * 128 + k0 + ac4]);
            *reinterpret_cast<float4*>(&As[ar][ac4]) = v;
            int br = idx >> 5, bc4 = (idx & 31) * 4;
            float4 w = *reinterpret_cast<const float4*>(&W[(size_t)(k0 + br) * 128 + bc4]);
            *reinterpret_cast<float4*>(&Bs[br][bc4]) = w;
        }
        __syncthreads();
#pragma unroll
        for (int ks = 0; ks < 4; ks++) {
            int k = ks * 8;
            uint32_t ah[2][4], al[2][4];
#pragma unroll
            for (int mt = 0; mt < 2; mt++) {
                int r0 = wr * 32 + mt * 16 + lq;
                float x0 = As[r0][k + lr];
                float x1 = As[r0 + 8][k + lr];
                float x2 = As[r0][k + lr + 4];
                float x3 = As[r0 + 8][k + lr + 4];
                ah[mt][0] = f2tf32(x0); al[mt][0] = f2tf32(x0 - __uint_as_float(ah[mt][0]));
                ah[mt][1] = f2tf32(x1); al[mt][1] = f2tf32(x1 - __uint_as_float(ah[mt][1]));
                ah[mt][2] = f2tf32(x2); al[mt][2] = f2tf32(x2 - __uint_as_float(ah[mt][2]));
                ah[mt][3] = f2tf32(x3); al[mt][3] = f2tf32(x3 - __uint_as_float(ah[mt][3]));
            }
#pragma unroll
            for (int nt = 0; nt < 8; nt++) {
                int ncol = wc * 64 + nt * 8 + lq;
                float y0 = Bs[k + lr][ncol];
                float y1 = Bs[k + lr + 4][ncol];
                uint32_t bh[2], bl[2];
                bh[0] = f2tf32(y0); bl[0] = f2tf32(y0 - __uint_as_float(bh[0]));
                bh[1] = f2tf32(y1); bl[1] = f2tf32(y1 - __uint_as_float(bh[1]));
#pragma unroll
                for (int mt = 0; mt < 2; mt++) {
                    mma_tf32(c[mt][nt], ah[mt], bh);
                    mma_tf32(c[mt][nt], ah[mt], bl);
                    mma_tf32(c[mt][nt], al[mt], bh);
                }
            }
        }
        __syncthreads();
    }

    // store C:  c0,c1 -> (r, cc..cc+1),  c2,c3 -> (r+8, cc..cc+1)
#pragma unroll
    for (int mt = 0; mt < 2; mt++) {
        int r0 = block_row + wr * 32 + mt * 16 + lq;
#pragma unroll
        for (int nt = 0; nt < 8; nt++) {
            int cc = wc * 64 + nt * 8 + lr * 2;
            if (r0 < M)
                *reinterpret_cast<float2*>(&C[(size_t)r0 * 128 + cc]) =
                    make_float2(c[mt][nt][0], c[mt][nt][1]);
            if (r0 + 8 < M)
                *reinterpret_cast<float2*>(&C[(size_t)(r0 + 8) * 128 + cc]) =
                    make_float2(c[mt][nt][2], c[mt][nt][3]);
        }
    }

    // fused e_src / e_dst epilogue; warp-col == head
#pragma unroll
    for (int mt = 0; mt < 2; mt++) {
#pragma unroll
        for (int half = 0; half < 2; half++) {      // row r0 (c0,c1) / r0+8 (c2,c3)
            float ps = 0.f, pd = 0.f;
#pragma unroll
            for (int nt = 0; nt < 8; nt++) {
                int cc = wc * 64 + nt * 8 + lr * 2;
                float v0 = c[mt][nt][half * 2 + 0];
                float v1 = c[mt][nt][half * 2 + 1];
                ps += v0 * av_src[cc] + v1 * av_src[cc + 1];
                pd += v0 * av_dst[cc] + v1 * av_dst[cc + 1];
            }
            // reduce across the 4-lane quad (same lq, lr = 0..3)
            ps += __shfl_xor_sync(0xffffffffu, ps, 1);
            pd += __shfl_xor_sync(0xffffffffu, pd, 1);
            ps += __shfl_xor_sync(0xffffffffu, ps, 2);
            pd += __shfl_xor_sync(0xffffffffu, pd, 2);
            int row = block_row + wr * 32 + mt * 16 + lq + half * 8;
            if (lr == 0 && row < M) {
                g_es[2 * row + wc] = ps;
                g_ed[2 * row + wc] = pd;
            }
        }
    }
}

__device__ __forceinline__ float lrelu(float x) { return x > 0.f ? x : 0.2f * x; }

// ---------------- fused softmax-aggregate (warp per dst node) ----------------
__global__ __launch_bounds__(256) void agg_kernel(
    const float* __restrict__ h, const float* __restrict__ bias,
    float* __restrict__ out, int n)
{
    int w = (blockIdx.x * blockDim.x + threadIdx.x) >> 5;
    int lane = threadIdx.x & 31;
    if (w >= n) return;
    int start = g_rowptr[w], end = g_rowptr[w + 1];
    int deg = end - start;
    const float2* es2 = reinterpret_cast<const float2*>(g_es);
    const float2* ed2 = reinterpret_cast<const float2*>(g_ed);
    float2 ed = ed2[w];

    float acc0 = 0.f, acc1 = 0.f, acc2 = 0.f, acc3 = 0.f;
    float den0 = 0.f, den1 = 0.f;
    const float4* h4 = reinterpret_cast<const float4*>(h);
    bool head0 = (lane < 16);

    if (deg <= 32) {
        int s = 0; float l0 = -3.0e38f, l1 = -3.0e38f;
        if (lane < deg) {
            s = g_col[start + lane];
            float2 es = es2[s];
            l0 = lrelu(es.x + ed.x);
            l1 = lrelu(es.y + ed.y);
        }
        float m0 = l0, m1 = l1;
#pragma unroll
        for (int o = 16; o; o >>= 1) {
            m0 = fmaxf(m0, __shfl_xor_sync(0xffffffffu, m0, o));
            m1 = fmaxf(m1, __shfl_xor_sync(0xffffffffu, m1, o));
        }
        float w0 = 0.f, w1 = 0.f;
        if (lane < deg) { w0 = __expf(l0 - m0); w1 = __expf(l1 - m1); }
        den0 = w0; den1 = w1;
#pragma unroll 4
        for (int k = 0; k < deg; k++) {
            int   ss  = __shfl_sync(0xffffffffu, s,  k);
            float wk0 = __shfl_sync(0xffffffffu, w0, k);
            float wk1 = __shfl_sync(0xffffffffu, w1, k);
            float wk  = head0 ? wk0 : wk1;
            float4 hv = h4[(size_t)ss * 32 + lane];
            acc0 += wk * hv.x; acc1 += wk * hv.y;
            acc2 += wk * hv.z; acc3 += wk * hv.w;
        }
    } else {
        float m0 = -3.0e38f, m1 = -3.0e38f;
        for (int j = start + lane; j < end; j += 32) {
            int s = g_col[j];
            float2 es = es2[s];
            m0 = fmaxf(m0, lrelu(es.x + ed.x));
            m1 = fmaxf(m1, lrelu(es.y + ed.y));
        }
#pragma unroll
        for (int o = 16; o; o >>= 1) {
            m0 = fmaxf(m0, __shfl_xor_sync(0xffffffffu, m0, o));
            m1 = fmaxf(m1, __shfl_xor_sync(0xffffffffu, m1, o));
        }
        for (int chunk = start; chunk < end; chunk += 32) {
            int j = chunk + lane;
            int s = 0; float w0 = 0.f, w1 = 0.f;
            if (j < end) {
                int sc = g_col[j];
                s = sc;
                float2 es = es2[sc];
                w0 = __expf(lrelu(es.x + ed.x) - m0);
                w1 = __expf(lrelu(es.y + ed.y) - m1);
            }
            den0 += w0; den1 += w1;
            int cnt = min(32, end - chunk);
#pragma unroll 4
            for (int k = 0; k < cnt; k++) {
                int   ss  = __shfl_sync(0xffffffffu, s,  k);
                float wk0 = __shfl_sync(0xffffffffu, w0, k);
                float wk1 = __shfl_sync(0xffffffffu, w1, k);
                float wk  = head0 ? wk0 : wk1;
                float4 hv = h4[(size_t)ss * 32 + lane];
                acc0 += wk * hv.x; acc1 += wk * hv.y;
                acc2 += wk * hv.z; acc3 += wk * hv.w;
            }
        }
    }

#pragma unroll
    for (int o = 16; o; o >>= 1) {
        den0 += __shfl_xor_sync(0xffffffffu, den0, o);
        den1 += __shfl_xor_sync(0xffffffffu, den1, o);
    }
    float inv = 1.0f / (head0 ? den0 : den1);
    float4 bb = reinterpret_cast<const float4*>(bias)[lane];
    float o0 = acc0 * inv + bb.x;
    float o1 = acc1 * inv + bb.y;
    float o2 = acc2 * inv + bb.z;
    float o3 = acc3 * inv + bb.w;
    o0 = o0 > 0.f ? o0 : expm1f(o0);
    o1 = o1 > 0.f ? o1 : expm1f(o1);
    o2 = o2 > 0.f ? o2 : expm1f(o2);
    o3 = o3 > 0.f ? o3 : expm1f(o3);
    reinterpret_cast<float4*>(out)[(size_t)w * 32 + lane] = make_float4(o0, o1, o2, o3);
}

// ---------------- host ----------------
extern "C" void kernel_launch(void* const* d_in, const int* in_sizes, int n_in,
                              void* d_out, int out_size)
{
    const float* x   = (const float*)d_in[0];
    const int*   ei  = (const int*)d_in[1];
    const float* W1  = (const float*)d_in[2];
    const float* as1 = (const float*)d_in[3];
    const float* ad1 = (const float*)d_in[4];
    const float* b1  = (const float*)d_in[5];
    const float* W2  = (const float*)d_in[6];
    const float* as2 = (const float*)d_in[7];
    const float* ad2 = (const float*)d_in[8];
    const float* b2  = (const float*)d_in[9];
    const float* W3  = (const float*)d_in[10];
    const float* as3 = (const float*)d_in[11];
    const float* ad3 = (const float*)d_in[12];
    const float* b3  = (const float*)d_in[13];
    float*       out = (float*)d_out;

    int n = in_sizes[0] / FDIM;          // 50000
    int E = in_sizes[1] / 2;             // 800000

    void* pA; cudaGetSymbolAddress(&pA, g_bufA);
    void* pB; cudaGetSymbolAddress(&pB, g_bufB);
    float* bufA = (float*)pA;
    float* bufB = (float*)pB;

    int nblkNodes = (n + 255) / 256;
    int nblkEdges = (E + n + 255) / 256;
    int nblkWarp  = (n * 32 + 255) / 256;
    int nblkGemm  = (n + 127) / 128;

    // launches 0..2: CSR front half
    zero_counts_kernel<<<nblkNodes, 256>>>(n);
    hist_kernel<<<nblkEdges, 256>>>(ei, E, n);
    scan_kernel<<<1, 1024>>>(n);
    // launch 3: sgemm1 (profiled by ncu capture offset)
    sgemm128_kernel<<<nblkGemm, 256>>>(x, W1, as1, ad1, bufA, n);
    // launch 4: scatter completes CSR before agg1
    scatter_kernel<<<nblkEdges, 256>>>(ei, E, n);
    // launch 5: agg1
    agg_kernel<<<nblkWarp, 256>>>(bufA, b1, bufB, n);
    // layer 2
    sgemm128_kernel<<<nblkGemm, 256>>>(bufB, W2, as2, ad2, bufA, n);
    agg_kernel<<<nblkWarp, 256>>>(bufA, b2, bufB, n);
    // layer 3
    sgemm128_kernel<<<nblkGemm, 256>>>(bufB, W3, as3, ad3, bufA, n);
    agg_kernel<<<nblkWarp, 256>>>(bufA, b3, out, n);
}

// round 11
// speedup vs baseline: 1.5381x; 1.0364x over previous
#include <cuda_runtime.h>
#include <cuda_fp16.h>
#include <math.h>
#include <cstdint>
#include <cstddef>

#define NN       50000
#define EE       800000
#define ETOT     (EE + NN)
#define FDIM     128

// ---------------- scratch ----------------
__device__ __half g_h[(size_t)NN * FDIM];     // fp16 feature buffer (agg gather input)
__device__ float  g_bufB[(size_t)NN * FDIM];  // fp32 agg output (next GEMM input)
__device__ float  g_es[NN * 2];
__device__ float  g_ed[NN * 2];
__device__ int    g_rowptr[NN + 1];
__device__ int    g_wp[NN];
__device__ int    g_col[ETOT];

// ---------------- CSR build ----------------
__global__ void zero_counts_kernel(int n) {
    int i = blockIdx.x * blockDim.x + threadIdx.x;
    if (i < n) g_wp[i] = 0;
}

__global__ void hist_kernel(const int* __restrict__ ei, int E, int n) {
    int e = blockIdx.x * blockDim.x + threadIdx.x;
    int etot = E + n;
    if (e >= etot) return;
    int d = (e < E) ? ei[E + e] : (e - E);
    atomicAdd(&g_wp[d], 1);
}

__global__ __launch_bounds__(1024) void scan_kernel(int n) {
    __shared__ int wsum[32];
    __shared__ int carry_sh;
    int lane = threadIdx.x & 31, wid = threadIdx.x >> 5;
    if (threadIdx.x == 0) carry_sh = 0;
    __syncthreads();
    for (int base = 0; base < n; base += 4096) {
        int idx = base + threadIdx.x * 4;
        int v0 = (idx + 0 < n) ? g_wp[idx + 0] : 0;
        int v1 = (idx + 1 < n) ? g_wp[idx + 1] : 0;
        int v2 = (idx + 2 < n) ? g_wp[idx + 2] : 0;
        int v3 = (idx + 3 < n) ? g_wp[idx + 3] : 0;
        int tsum = v0 + v1 + v2 + v3;
        int x = tsum;
#pragma unroll
        for (int off = 1; off < 32; off <<= 1) {
            int y = __shfl_up_sync(0xffffffffu, x, off);
            if (lane >= off) x += y;
        }
        if (lane == 31) wsum[wid] = x;
        __syncthreads();
        if (wid == 0) {
            int ws = wsum[lane];
#pragma unroll
            for (int off = 1; off < 32; off <<= 1) {
                int y = __shfl_up_sync(0xffffffffu, ws, off);
                if (lane >= off) ws += y;
            }
            wsum[lane] = ws;
        }
        __syncthreads();
        int carry = carry_sh;
        int excl = carry + (wid ? wsum[wid - 1] : 0) + (x - tsum);
        if (idx + 0 < n) { g_rowptr[idx + 0] = excl; g_wp[idx + 0] = excl; } excl += v0;
        if (idx + 1 < n) { g_rowptr[idx + 1] = excl; g_wp[idx + 1] = excl; } excl += v1;
        if (idx + 2 < n) { g_rowptr[idx + 2] = excl; g_wp[idx + 2] = excl; } excl += v2;
        if (idx + 3 < n) { g_rowptr[idx + 3] = excl; g_wp[idx + 3] = excl; }
        int total = wsum[31];
        __syncthreads();
        if (threadIdx.x == 0) carry_sh = carry + total;
        __syncthreads();
    }
    if (threadIdx.x == 0) g_rowptr[n] = carry_sh;
}

__global__ void scatter_kernel(const int* __restrict__ ei, int E, int n) {
    int e = blockIdx.x * blockDim.x + threadIdx.x;
    int etot = E + n;
    if (e >= etot) return;
    int s, d;
    if (e < E) { s = ei[e]; d = ei[E + e]; }
    else       { s = e - E; d = s; }
    int p = atomicAdd(&g_wp[d], 1);
    g_col[p] = s;
}

// ---------------- tf32 helpers ----------------
__device__ __forceinline__ uint32_t f2tf32(float x) {
    uint32_t r;
    asm("cvt.rna.tf32.f32 %0, %1;" : "=r"(r) : "f"(x));
    return r;
}
__device__ __forceinline__ void mma_tf32(float* c, const uint32_t* a, const uint32_t* b) {
    asm volatile(
        "mma.sync.aligned.m16n8k8.row.col.f32.tf32.tf32.f32 "
        "{%0,%1,%2,%3},{%4,%5,%6,%7},{%8,%9},{%0,%1,%2,%3};"
        : "+f"(c[0]), "+f"(c[1]), "+f"(c[2]), "+f"(c[3])
        : "r"(a[0]), "r"(a[1]), "r"(a[2]), "r"(a[3]), "r"(b[0]), "r"(b[1]));
}

// ---------------- 3xTF32 tensor GEMM -> fp16 C + fused e epilogue ----------------
// Ch[M,128](fp16) = A[M,128](fp32) @ W[128,128]; es/ed from fp32 accumulators.
__global__ __launch_bounds__(256, 2) void sgemm128_kernel(
    const float* __restrict__ A, const float* __restrict__ W,
    const float* __restrict__ av_src, const float* __restrict__ av_dst,
    __half* __restrict__ Ch, int M)
{
    __shared__ float As[128][36];
    __shared__ float Bs[32][136];
    int block_row = blockIdx.x * 128;
    int tid  = threadIdx.x;
    int lane = tid & 31;
    int warp = tid >> 5;
    int wr = warp >> 1;
    int wc = warp & 1;              // == attention head
    int lq = lane >> 2;
    int lr = lane & 3;

    float c[2][8][4];
#pragma unroll
    for (int mt = 0; mt < 2; mt++)
#pragma unroll
        for (int nt = 0; nt < 8; nt++)
#pragma unroll
            for (int i = 0; i < 4; i++) c[mt][nt][i] = 0.f;

    for (int kc = 0; kc < 4; kc++) {
        int k0 = kc * 32;
#pragma unroll
        for (int i = 0; i < 4; i++) {
            int idx = tid + i * 256;
            int ar = idx >> 3, ac4 = (idx & 7) * 4;
            int gr = block_row + ar;
            float4 v = make_float4(0.f, 0.f, 0.f, 0.f);
            if (gr < M) v = *reinterpret_cast<const float4*>(&A[(size_t)gr * 128 + k0 + ac4]);
            *reinterpret_cast<float4*>(&As[ar][ac4]) = v;
            int br = idx >> 5, bc4 = (idx & 31) * 4;
            float4 w = *reinterpret_cast<const float4*>(&W[(size_t)(k0 + br) * 128 + bc4]);
            *reinterpret_cast<float4*>(&Bs[br][bc4]) = w;
        }
        __syncthreads();
#pragma unroll
        for (int ks = 0; ks < 4; ks++) {
            int k = ks * 8;
            uint32_t ah[2][4], al[2][4];
#pragma unroll
            for (int mt = 0; mt < 2; mt++) {
                int r0 = wr * 32 + mt * 16 + lq;
                float x0 = As[r0][k + lr];
                float x1 = As[r0 + 8][k + lr];
                float x2 = As[r0][k + lr + 4];
                float x3 = As[r0 + 8][k + lr + 4];
                ah[mt][0] = f2tf32(x0); al[mt][0] = f2tf32(x0 - __uint_as_float(ah[mt][0]));
                ah[mt][1] = f2tf32(x1); al[mt][1] = f2tf32(x1 - __uint_as_float(ah[mt][1]));
                ah[mt][2] = f2tf32(x2); al[mt][2] = f2tf32(x2 - __uint_as_float(ah[mt][2]));
                ah[mt][3] = f2tf32(x3); al[mt][3] = f2tf32(x3 - __uint_as_float(ah[mt][3]));
            }
#pragma unroll
            for (int nt = 0; nt < 8; nt++) {
                int ncol = wc * 64 + nt * 8 + lq;
                float y0 = Bs[k + lr][ncol];
                float y1 = Bs[k + lr + 4][ncol];
                uint32_t bh[2], bl[2];
                bh[0] = f2tf32(y0); bl[0] = f2tf32(y0 - __uint_as_float(bh[0]));
                bh[1] = f2tf32(y1); bl[1] = f2tf32(y1 - __uint_as_float(bh[1]));
#pragma unroll
                for (int mt = 0; mt < 2; mt++) {
                    mma_tf32(c[mt][nt], ah[mt], bh);
                    mma_tf32(c[mt][nt], ah[mt], bl);
                    mma_tf32(c[mt][nt], al[mt], bh);
                }
            }
        }
        __syncthreads();
    }

    // store C as fp16 (half2 per register pair)
#pragma unroll
    for (int mt = 0; mt < 2; mt++) {
        int r0 = block_row + wr * 32 + mt * 16 + lq;
#pragma unroll
        for (int nt = 0; nt < 8; nt++) {
            int cc = wc * 64 + nt * 8 + lr * 2;
            if (r0 < M)
                *reinterpret_cast<__half2*>(&Ch[(size_t)r0 * 128 + cc]) =
                    __floats2half2_rn(c[mt][nt][0], c[mt][nt][1]);
            if (r0 + 8 < M)
                *reinterpret_cast<__half2*>(&Ch[(size_t)(r0 + 8) * 128 + cc]) =
                    __floats2half2_rn(c[mt][nt][2], c[mt][nt][3]);
        }
    }

    // fused e_src / e_dst epilogue from fp32 accumulators; warp-col == head
#pragma unroll
    for (int mt = 0; mt < 2; mt++) {
#pragma unroll
        for (int half = 0; half < 2; half++) {
            float ps = 0.f, pd = 0.f;
#pragma unroll
            for (int nt = 0; nt < 8; nt++) {
                int cc = wc * 64 + nt * 8 + lr * 2;
                float v0 = c[mt][nt][half * 2 + 0];
                float v1 = c[mt][nt][half * 2 + 1];
                ps += v0 * av_src[cc] + v1 * av_src[cc + 1];
                pd += v0 * av_dst[cc] + v1 * av_dst[cc + 1];
            }
            ps += __shfl_xor_sync(0xffffffffu, ps, 1);
            pd += __shfl_xor_sync(0xffffffffu, pd, 1);
            ps += __shfl_xor_sync(0xffffffffu, ps, 2);
            pd += __shfl_xor_sync(0xffffffffu, pd, 2);
            int row = block_row + wr * 32 + mt * 16 + lq + half * 8;
            if (lr == 0 && row < M) {
                g_es[2 * row + wc] = ps;
                g_ed[2 * row + wc] = pd;
            }
        }
    }
}

__device__ __forceinline__ float lrelu(float x) { return x > 0.f ? x : 0.2f * x; }

// ---------------- fused softmax-aggregate (warp per dst node, fp16 gather) ----------------
__global__ __launch_bounds__(256) void agg_kernel(
    const __half* __restrict__ h, const float* __restrict__ bias,
    float* __restrict__ out, int n)
{
    int w = (blockIdx.x * blockDim.x + threadIdx.x) >> 5;
    int lane = threadIdx.x & 31;
    if (w >= n) return;
    int start = g_rowptr[w], end = g_rowptr[w + 1];
    int deg = end - start;
    const float2* es2 = reinterpret_cast<const float2*>(g_es);
    const float2* ed2 = reinterpret_cast<const float2*>(g_ed);
    float2 ed = ed2[w];

    float acc0 = 0.f, acc1 = 0.f, acc2 = 0.f, acc3 = 0.f;
    float den0 = 0.f, den1 = 0.f;
    // lane covers cols 4*lane..4*lane+3 -> one uint2; row = 128 half = 32 uint2
    const uint2* h8 = reinterpret_cast<const uint2*>(h);
    bool head0 = (lane < 16);

    if (deg <= 32) {
        int s = 0; float l0 = -3.0e38f, l1 = -3.0e38f;
        if (lane < deg) {
            s = g_col[start + lane];
            float2 es = es2[s];
            l0 = lrelu(es.x + ed.x);
            l1 = lrelu(es.y + ed.y);
        }
        float m0 = l0, m1 = l1;
#pragma unroll
        for (int o = 16; o; o >>= 1) {
            m0 = fmaxf(m0, __shfl_xor_sync(0xffffffffu, m0, o));
            m1 = fmaxf(m1, __shfl_xor_sync(0xffffffffu, m1, o));
        }
        float w0 = 0.f, w1 = 0.f;
        if (lane < deg) { w0 = __expf(l0 - m0); w1 = __expf(l1 - m1); }
        den0 = w0; den1 = w1;
#pragma unroll 4
        for (int k = 0; k < deg; k++) {
            int   ss  = __shfl_sync(0xffffffffu, s,  k);
            float wk0 = __shfl_sync(0xffffffffu, w0, k);
            float wk1 = __shfl_sync(0xffffffffu, w1, k);
            float wk  = head0 ? wk0 : wk1;
            uint2 u = h8[(size_t)ss * 32 + lane];
            float2 f0 = __half22float2(*reinterpret_cast<const __half2*>(&u.x));
            float2 f1 = __half22float2(*reinterpret_cast<const __half2*>(&u.y));
            acc0 += wk * f0.x; acc1 += wk * f0.y;
            acc2 += wk * f1.x; acc3 += wk * f1.y;
        }
    } else {
        float m0 = -3.0e38f, m1 = -3.0e38f;
        for (int j = start + lane; j < end; j += 32) {
            int s = g_col[j];
            float2 es = es2[s];
            m0 = fmaxf(m0, lrelu(es.x + ed.x));
            m1 = fmaxf(m1, lrelu(es.y + ed.y));
        }
#pragma unroll
        for (int o = 16; o; o >>= 1) {
            m0 = fmaxf(m0, __shfl_xor_sync(0xffffffffu, m0, o));
            m1 = fmaxf(m1, __shfl_xor_sync(0xffffffffu, m1, o));
        }
        for (int chunk = start; chunk < end; chunk += 32) {
            int j = chunk + lane;
            int s = 0; float w0 = 0.f, w1 = 0.f;
            if (j < end) {
                int sc = g_col[j];
                s = sc;
                float2 es = es2[sc];
                w0 = __expf(lrelu(es.x + ed.x) - m0);
                w1 = __expf(lrelu(es.y + ed.y) - m1);
            }
            den0 += w0; den1 += w1;
            int cnt = min(32, end - chunk);
#pragma unroll 4
            for (int k = 0; k < cnt; k++) {
                int   ss  = __shfl_sync(0xffffffffu, s,  k);
                float wk0 = __shfl_sync(0xffffffffu, w0, k);
                float wk1 = __shfl_sync(0xffffffffu, w1, k);
                float wk  = head0 ? wk0 : wk1;
                uint2 u = h8[(size_t)ss * 32 + lane];
                float2 f0 = __half22float2(*reinterpret_cast<const __half2*>(&u.x));
                float2 f1 = __half22float2(*reinterpret_cast<const __half2*>(&u.y));
                acc0 += wk * f0.x; acc1 += wk * f0.y;
                acc2 += wk * f1.x; acc3 += wk * f1.y;
            }
        }
    }

#pragma unroll
    for (int o = 16; o; o >>= 1) {
        den0 += __shfl_xor_sync(0xffffffffu, den0, o);
        den1 += __shfl_xor_sync(0xffffffffu, den1, o);
    }
    float inv = 1.0f / (head0 ? den0 : den1);
    float4 bb = reinterpret_cast<const float4*>(bias)[lane];
    float o0 = acc0 * inv + bb.x;
    float o1 = acc1 * inv + bb.y;
    float o2 = acc2 * inv + bb.z;
    float o3 = acc3 * inv + bb.w;
    o0 = o0 > 0.f ? o0 : expm1f(o0);
    o1 = o1 > 0.f ? o1 : expm1f(o1);
    o2 = o2 > 0.f ? o2 : expm1f(o2);
    o3 = o3 > 0.f ? o3 : expm1f(o3);
    reinterpret_cast<float4*>(out)[(size_t)w * 32 + lane] = make_float4(o0, o1, o2, o3);
}

// ---------------- host ----------------
extern "C" void kernel_launch(void* const* d_in, const int* in_sizes, int n_in,
                              void* d_out, int out_size)
{
    const float* x   = (const float*)d_in[0];
    const int*   ei  = (const int*)d_in[1];
    const float* W1  = (const float*)d_in[2];
    const float* as1 = (const float*)d_in[3];
    const float* ad1 = (const float*)d_in[4];
    const float* b1  = (const float*)d_in[5];
    const float* W2  = (const float*)d_in[6];
    const float* as2 = (const float*)d_in[7];
    const float* ad2 = (const float*)d_in[8];
    const float* b2  = (const float*)d_in[9];
    const float* W3  = (const float*)d_in[10];
    const float* as3 = (const float*)d_in[11];
    const float* ad3 = (const float*)d_in[12];
    const float* b3  = (const float*)d_in[13];
    float*       out = (float*)d_out;

    int n = in_sizes[0] / FDIM;          // 50000
    int E = in_sizes[1] / 2;             // 800000

    void* pH; cudaGetSymbolAddress(&pH, g_h);
    void* pB; cudaGetSymbolAddress(&pB, g_bufB);
    __half* hbuf = (__half*)pH;
    float*  bufB = (float*)pB;

    int nblkNodes = (n + 255) / 256;
    int nblkEdges = (E + n + 255) / 256;
    int nblkWarp  = (n * 32 + 255) / 256;
    int nblkGemm  = (n + 127) / 128;

    // launches 0..2: CSR front half
    zero_counts_kernel<<<nblkNodes, 256>>>(n);
    hist_kernel<<<nblkEdges, 256>>>(ei, E, n);
    scan_kernel<<<1, 1024>>>(n);
    // launch 3: sgemm1 (ncu capture offset)
    sgemm128_kernel<<<nblkGemm, 256>>>(x, W1, as1, ad1, hbuf, n);
    // launch 4: scatter completes CSR before agg1
    scatter_kernel<<<nblkEdges, 256>>>(ei, E, n);
    // launch 5: agg1
    agg_kernel<<<nblkWarp, 256>>>(hbuf, b1, bufB, n);
    // layer 2
    sgemm128_kernel<<<nblkGemm, 256>>>(bufB, W2, as2, ad2, hbuf, n);
    agg_kernel<<<nblkWarp, 256>>>(hbuf, b2, bufB, n);
    // layer 3
    sgemm128_kernel<<<nblkGemm, 256>>>(bufB, W3, as3, ad3, hbuf, n);
    agg_kernel<<<nblkWarp, 256>>>(hbuf, b3, out, n);
}